// round 1
// baseline (speedup 1.0000x reference)
#include <cuda_runtime.h>
#include <math.h>

#define NSIDE 48
#define PITCH 52            // padded row stride (floats), 16B-aligned rows
#define NPIX  (NSIDE*NSIDE) // 2304
#define MAT   (NSIDE*PITCH) // 2496 floats per padded 48x48 matrix
#define NTHR  256
#define NITERS 5

// Block-wide sum reduction (256 threads = 8 warps)
__device__ __forceinline__ float block_sum(float v, float* red) {
    const int lane = threadIdx.x & 31;
    const int wid  = threadIdx.x >> 5;
    #pragma unroll
    for (int o = 16; o > 0; o >>= 1) v += __shfl_xor_sync(0xffffffffu, v, o);
    if (lane == 0) red[wid] = v;
    __syncthreads();
    if (wid == 0) {
        float x = (lane < (NTHR/32)) ? red[lane] : 0.0f;
        #pragma unroll
        for (int o = 4; o > 0; o >>= 1) x += __shfl_xor_sync(0xffffffffu, x, o);
        if (lane == 0) red[0] = x;
    }
    __syncthreads();
    float r = red[0];
    __syncthreads();
    return r;
}

// acc[3][3] += A[i0+r][:] . B[j0+c][:]   (rows of both operands; both matrices
// we ever pass are symmetric, so "dot of rows" == standard matmul)
__device__ __forceinline__ void mm3x3(const float* __restrict__ A,
                                      const float* __restrict__ B,
                                      int i0, int j0, float acc[9]) {
    const float* a0 = A + (i0+0)*PITCH;
    const float* a1 = A + (i0+1)*PITCH;
    const float* a2 = A + (i0+2)*PITCH;
    const float* b0 = B + (j0+0)*PITCH;
    const float* b1 = B + (j0+1)*PITCH;
    const float* b2 = B + (j0+2)*PITCH;
    #pragma unroll
    for (int k = 0; k < NSIDE; k += 4) {
        float4 A0 = *(const float4*)(a0 + k);
        float4 A1 = *(const float4*)(a1 + k);
        float4 A2 = *(const float4*)(a2 + k);
        float4 B0 = *(const float4*)(b0 + k);
        float4 B1 = *(const float4*)(b1 + k);
        float4 B2 = *(const float4*)(b2 + k);
        acc[0] = fmaf(A0.x,B0.x,fmaf(A0.y,B0.y,fmaf(A0.z,B0.z,fmaf(A0.w,B0.w,acc[0]))));
        acc[1] = fmaf(A0.x,B1.x,fmaf(A0.y,B1.y,fmaf(A0.z,B1.z,fmaf(A0.w,B1.w,acc[1]))));
        acc[2] = fmaf(A0.x,B2.x,fmaf(A0.y,B2.y,fmaf(A0.z,B2.z,fmaf(A0.w,B2.w,acc[2]))));
        acc[3] = fmaf(A1.x,B0.x,fmaf(A1.y,B0.y,fmaf(A1.z,B0.z,fmaf(A1.w,B0.w,acc[3]))));
        acc[4] = fmaf(A1.x,B1.x,fmaf(A1.y,B1.y,fmaf(A1.z,B1.z,fmaf(A1.w,B1.w,acc[4]))));
        acc[5] = fmaf(A1.x,B2.x,fmaf(A1.y,B2.y,fmaf(A1.z,B2.z,fmaf(A1.w,B2.w,acc[5]))));
        acc[6] = fmaf(A2.x,B0.x,fmaf(A2.y,B0.y,fmaf(A2.z,B0.z,fmaf(A2.w,B0.w,acc[6]))));
        acc[7] = fmaf(A2.x,B1.x,fmaf(A2.y,B1.y,fmaf(A2.z,B1.z,fmaf(A2.w,B1.w,acc[7]))));
        acc[8] = fmaf(A2.x,B2.x,fmaf(A2.y,B2.y,fmaf(A2.z,B2.z,fmaf(A2.w,B2.w,acc[8]))));
    }
}

#define ZERO9(a) do { _Pragma("unroll") for (int _q=0;_q<9;_q++) (a)[_q]=0.0f; } while(0)

__global__ void __launch_bounds__(NTHR, 1)
sinkhorn_kernel(const float* __restrict__ img_pred,
                const float* __restrict__ img_target,
                const float* __restrict__ cm,
                float* __restrict__ out)
{
    extern __shared__ float sm[];
    float* G     = sm;             // [48][52] Gaussian 1D kernel, symmetric
    float* G2    = sm + 1*MAT;     // [48][52] G * cost1d, symmetric
    float* At    = sm + 2*MAT;     // [48][52] transpose of exp(alpha) image
    float* Bt    = sm + 3*MAT;     // [48][52] transpose of exp(beta) image
    float* U     = sm + 4*MAT;     // [48][52] matmul intermediate
    float* alpha = sm + 5*MAT;     // [2304] u/eps
    float* beta  = alpha + NPIX;   // [2304] v/eps
    float* lu    = beta  + NPIX;   // [2304] log mass_source
    float* lv    = lu    + NPIX;   // [2304] log mass_target
    float* red   = lv    + NPIX;   // [32] reduction scratch

    const int tid = threadIdx.x;
    const int b   = blockIdx.x;

    // Build G, G2 from the actual cost_matrix input.
    // cost_matrix[(a*48)*2304 + b*48] == ((a-b)/48)^2  (pure y-term; x-term identical)
    for (int idx = tid; idx < NPIX; idx += NTHR) {
        int r = idx / NSIDE;
        int c = idx - r * NSIDE;
        float cy = cm[(size_t)r * NSIDE * NPIX + (size_t)c * NSIDE];
        float g  = __expf(-100.0f * cy);     // exp(-c/EPS), EPS=0.01
        G [r*PITCH + c] = g;
        G2[r*PITCH + c] = g * cy;
    }

    // Normalized log-marginals for this batch (channel 0)
    const float* p = img_pred   + (size_t)b * 3 * NPIX;
    const float* t = img_target + (size_t)b * 3 * NPIX;
    float sp = 0.0f, st = 0.0f;
    for (int i = tid; i < NPIX; i += NTHR) { sp += p[i] + 1e-9f; st += t[i] + 1e-9f; }
    sp = block_sum(sp, red);
    st = block_sum(st, red);
    const float isp = 1.0f / sp, ist = 1.0f / st;
    for (int i = tid; i < NPIX; i += NTHR) {
        lu[i] = __logf((p[i] + 1e-9f) * isp);
        lv[i] = __logf((t[i] + 1e-9f) * ist);
        alpha[i] = 0.0f;
        beta[i]  = 0.0f;
    }
    for (int i = tid; i < MAT; i += NTHR) Bt[i] = 1.0f;   // exp(beta)=1
    __syncthreads();

    const int i0 = 3 * (tid >> 4);   // 16x16 grid of 3x3 output tiles
    const int j0 = 3 * (tid & 15);
    float acc[9];

    #pragma unroll 1
    for (int it = 0; it < NITERS; it++) {
        // ---- u half-step: s = G * EB * G ----
        ZERO9(acc);
        mm3x3(G, Bt, i0, j0, acc);       // U = G * EB  (Bt[j][k] = EB[k][j])
        #pragma unroll
        for (int r = 0; r < 3; r++)
            #pragma unroll
            for (int c = 0; c < 3; c++)
                U[(i0+r)*PITCH + (j0+c)] = acc[3*r+c];
        __syncthreads();
        ZERO9(acc);
        mm3x3(U, G, i0, j0, acc);        // T = U * G (G symmetric)
        #pragma unroll
        for (int r = 0; r < 3; r++)
            #pragma unroll
            for (int c = 0; c < 3; c++) {
                int y = i0 + r, x = j0 + c, f = y*NSIDE + x;
                float ao = alpha[f];
                float an = lu[f] - __logf(__expf(ao) * acc[3*r+c] + 1e-6f) + ao;
                alpha[f] = an;
                At[x*PITCH + y] = __expf(an);   // transposed exp(alpha) image
            }
        __syncthreads();

        // ---- v half-step: t = G * EA * G (K symmetric) ----
        ZERO9(acc);
        mm3x3(G, At, i0, j0, acc);
        #pragma unroll
        for (int r = 0; r < 3; r++)
            #pragma unroll
            for (int c = 0; c < 3; c++)
                U[(i0+r)*PITCH + (j0+c)] = acc[3*r+c];
        __syncthreads();
        ZERO9(acc);
        mm3x3(U, G, i0, j0, acc);
        #pragma unroll
        for (int r = 0; r < 3; r++)
            #pragma unroll
            for (int c = 0; c < 3; c++) {
                int y = i0 + r, x = j0 + c, f = y*NSIDE + x;
                float bo = beta[f];
                float bn = lv[f] - __logf(__expf(bo) * acc[3*r+c] + 1e-6f) + bo;
                beta[f] = bn;
                Bt[x*PITCH + y] = __expf(bn);
            }
        __syncthreads();
    }

    // ---- final cost: sum_ij EA_i * (K.C)_ij * EB_j
    //      K.C = (G2 (x) G) + (G (x) G2), so
    //      cost = sum EA .* (G2*EB*G) + sum EA .* (G*EB*G2)
    float csum = 0.0f;

    ZERO9(acc);
    mm3x3(G2, Bt, i0, j0, acc);          // U = G2 * EB
    #pragma unroll
    for (int r = 0; r < 3; r++)
        #pragma unroll
        for (int c = 0; c < 3; c++)
            U[(i0+r)*PITCH + (j0+c)] = acc[3*r+c];
    __syncthreads();
    ZERO9(acc);
    mm3x3(U, G, i0, j0, acc);            // T1 = U * G
    #pragma unroll
    for (int r = 0; r < 3; r++)
        #pragma unroll
        for (int c = 0; c < 3; c++) {
            int f = (i0+r)*NSIDE + (j0+c);
            csum += __expf(alpha[f]) * acc[3*r+c];
        }
    __syncthreads();

    ZERO9(acc);
    mm3x3(G, Bt, i0, j0, acc);           // U = G * EB
    #pragma unroll
    for (int r = 0; r < 3; r++)
        #pragma unroll
        for (int c = 0; c < 3; c++)
            U[(i0+r)*PITCH + (j0+c)] = acc[3*r+c];
    __syncthreads();
    ZERO9(acc);
    mm3x3(U, G2, i0, j0, acc);           // T2 = U * G2
    #pragma unroll
    for (int r = 0; r < 3; r++)
        #pragma unroll
        for (int c = 0; c < 3; c++) {
            int f = (i0+r)*NSIDE + (j0+c);
            csum += __expf(alpha[f]) * acc[3*r+c];
        }
    __syncthreads();

    csum = block_sum(csum, red);
    if (tid == 0) out[b] = csum;
}

extern "C" void kernel_launch(void* const* d_in, const int* in_sizes, int n_in,
                              void* d_out, int out_size) {
    const float* img_pred   = (const float*)d_in[0];
    const float* img_target = (const float*)d_in[1];
    const float* cm         = (const float*)d_in[2];
    float* out = (float*)d_out;

    const int B = in_sizes[0] / (3 * NPIX);   // 32
    const int smem_bytes = (5*MAT + 4*NPIX + 32) * (int)sizeof(float);  // ~87KB

    cudaFuncSetAttribute(sinkhorn_kernel,
                         cudaFuncAttributeMaxDynamicSharedMemorySize, smem_bytes);
    sinkhorn_kernel<<<B, NTHR, smem_bytes>>>(img_pred, img_target, cm, out);
}

// round 3
// speedup vs baseline: 1.3092x; 1.3092x over previous
#include <cuda_runtime.h>
#include <stdint.h>

#define NSIDE 48
#define PITCH 52                 // padded row stride (floats); 16B-aligned rows
#define NPIX  (NSIDE*NSIDE)      // 2304
#define MAT   (NSIDE*PITCH)      // 2496
#define CSIZE 4                  // CTAs per cluster (per batch)
#define RPC   (NSIDE/CSIZE)      // 12 rows owned per CTA
#define NTHR  192                // 12 tile-rows x 16 tile-cols, 1x3 tiles
#define NWARP (NTHR/32)
#define NITERS 5

__device__ __forceinline__ uint32_t smem_u32(const void* p) {
    return (uint32_t)__cvta_generic_to_shared(p);
}

// Store 4B to the same smem offset in a peer CTA of the cluster.
__device__ __forceinline__ void st_remote(uint32_t laddr, uint32_t rank, float v) {
    uint32_t raddr;
    asm volatile("mapa.shared::cluster.u32 %0, %1, %2;"
                 : "=r"(raddr) : "r"(laddr), "r"(rank));
    asm volatile("st.shared::cluster.b32 [%0], %1;"
                 :: "r"(raddr), "r"(__float_as_uint(v)) : "memory");
}

__device__ __forceinline__ void cluster_sync_() {
    asm volatile("barrier.cluster.arrive.aligned;" ::: "memory");
    asm volatile("barrier.cluster.wait.aligned;" ::: "memory");
}

// Block-wide sum (192 threads = 6 warps)
__device__ __forceinline__ float block_sum(float v, float* red) {
    const int lane = threadIdx.x & 31;
    const int wid  = threadIdx.x >> 5;
    #pragma unroll
    for (int o = 16; o > 0; o >>= 1) v += __shfl_xor_sync(0xffffffffu, v, o);
    if (lane == 0) red[wid] = v;
    __syncthreads();
    if (wid == 0) {
        float x = (lane < NWARP) ? red[lane] : 0.0f;
        #pragma unroll
        for (int o = 4; o > 0; o >>= 1) x += __shfl_xor_sync(0xffffffffu, x, o);
        if (lane == 0) red[0] = x;
    }
    __syncthreads();
    float r = red[0];
    __syncthreads();
    return r;
}

// acc[0..2] += a[:] . b{0,1,2}[:]  over k=0..47 (row-dot-row; all operands symmetric
// or pre-transposed, so this is a standard matmul step)
__device__ __forceinline__ void mm1x3(const float* __restrict__ a,
                                      const float* __restrict__ b0,
                                      float acc[3]) {
    const float* b1 = b0 + PITCH;
    const float* b2 = b0 + 2*PITCH;
    #pragma unroll
    for (int k = 0; k < NSIDE; k += 4) {
        float4 av = *(const float4*)(a  + k);
        float4 B0 = *(const float4*)(b0 + k);
        float4 B1 = *(const float4*)(b1 + k);
        float4 B2 = *(const float4*)(b2 + k);
        acc[0] = fmaf(av.x,B0.x,fmaf(av.y,B0.y,fmaf(av.z,B0.z,fmaf(av.w,B0.w,acc[0]))));
        acc[1] = fmaf(av.x,B1.x,fmaf(av.y,B1.y,fmaf(av.z,B1.z,fmaf(av.w,B1.w,acc[1]))));
        acc[2] = fmaf(av.x,B2.x,fmaf(av.y,B2.y,fmaf(av.z,B2.z,fmaf(av.w,B2.w,acc[2]))));
    }
}

__global__ void __launch_bounds__(NTHR, 1) __cluster_dims__(CSIZE, 1, 1)
sinkhorn_kernel(const float* __restrict__ img_pred,
                const float* __restrict__ img_target,
                const float* __restrict__ cm,
                float* __restrict__ out)
{
    __shared__ float G[MAT];        // 1D Gaussian kernel exp(-c1d/eps), symmetric
    __shared__ float G2[MAT];       // G * c1d, symmetric
    __shared__ float At[MAT];       // transpose of exp(alpha) image (replicated per CTA)
    __shared__ float Bt[MAT];       // transpose of exp(beta) image  (replicated per CTA)
    __shared__ float U[RPC*PITCH];  // own rows of first-stage matmul
    __shared__ float red[24];       // [0..7] block reduce, [16..19] cluster partials

    const int tid   = threadIdx.x;
    const int rank  = blockIdx.x & (CSIZE-1);
    const int batch = blockIdx.x / CSIZE;
    const int trow  = tid >> 4;            // 0..11 local output row
    const int j0    = 3 * (tid & 15);      // output col group
    const int ig    = rank * RPC + trow;   // global output row

    // ---- build G, G2 from the cost_matrix input ----
    // cost_matrix[(a*48)*2304 + b*48] == ((a-b)/48)^2  (pure y-term of the separable cost)
    for (int idx = tid; idx < NPIX; idx += NTHR) {
        int r = idx / NSIDE, c = idx - r * NSIDE;
        float cy = cm[(size_t)r * NSIDE * NPIX + (size_t)c * NSIDE];
        float g  = __expf(-100.0f * cy);       // exp(-c/EPS), EPS=0.01
        G [r*PITCH + c] = g;
        G2[r*PITCH + c] = g * cy;
    }
    for (int i = tid; i < MAT; i += NTHR) Bt[i] = 1.0f;   // exp(beta)=1

    // ---- normalized marginals (channel 0); each CTA computes its full sums ----
    const float* p = img_pred   + (size_t)batch * 3 * NPIX;
    const float* t = img_target + (size_t)batch * 3 * NPIX;
    float sp = 0.0f, st = 0.0f;
    for (int i = tid; i < NPIX; i += NTHR) { sp += p[i]; st += t[i]; }
    sp = block_sum(sp, red) + NPIX * 1e-9f;
    st = block_sum(st, red) + NPIX * 1e-9f;
    const float isp = 1.0f / sp, ist = 1.0f / st;

    // per-thread pixels: (y=ig, x=j0..j0+2). Pure scaling form of Sinkhorn:
    //   ea' = eu*ea/(ea*T + 1e-6)  ==  exp( lu - log(exp(a)*T + 1e-6) + a )
    float eu[3], ev[3], ea[3], eb[3];
    #pragma unroll
    for (int c = 0; c < 3; c++) {
        int pix = ig * NSIDE + j0 + c;
        eu[c] = (p[pix] + 1e-9f) * isp;
        ev[c] = (t[pix] + 1e-9f) * ist;
        ea[c] = 1.0f;
        eb[c] = 1.0f;
    }
    __syncthreads();

    float acc[3];
    #pragma unroll 1
    for (int it = 0; it < NITERS; it++) {
        // ---- u half-step: T = G * EB * G  (own rows) ----
        acc[0]=acc[1]=acc[2]=0.0f;
        mm1x3(G + ig*PITCH, Bt + j0*PITCH, acc);          // U = G * EB (B operand transposed)
        U[trow*PITCH + j0+0] = acc[0];
        U[trow*PITCH + j0+1] = acc[1];
        U[trow*PITCH + j0+2] = acc[2];
        __syncthreads();
        acc[0]=acc[1]=acc[2]=0.0f;
        mm1x3(U + trow*PITCH, G + j0*PITCH, acc);         // T = U * G (G symmetric)
        #pragma unroll
        for (int c = 0; c < 3; c++) {
            float e = __fdividef(eu[c] * ea[c], fmaf(ea[c], acc[c], 1e-6f));
            ea[c] = e;
            int off = (j0 + c) * PITCH + ig;              // transposed store
            At[off] = e;
            uint32_t la = smem_u32(&At[off]);
            #pragma unroll
            for (int rr = 1; rr < CSIZE; rr++)
                st_remote(la, (uint32_t)((rank + rr) & (CSIZE-1)), e);
        }
        cluster_sync_();

        // ---- v half-step: T = G * EA * G  (K symmetric) ----
        acc[0]=acc[1]=acc[2]=0.0f;
        mm1x3(G + ig*PITCH, At + j0*PITCH, acc);
        U[trow*PITCH + j0+0] = acc[0];
        U[trow*PITCH + j0+1] = acc[1];
        U[trow*PITCH + j0+2] = acc[2];
        __syncthreads();
        acc[0]=acc[1]=acc[2]=0.0f;
        mm1x3(U + trow*PITCH, G + j0*PITCH, acc);
        #pragma unroll
        for (int c = 0; c < 3; c++) {
            float e = __fdividef(ev[c] * eb[c], fmaf(eb[c], acc[c], 1e-6f));
            eb[c] = e;
            int off = (j0 + c) * PITCH + ig;
            Bt[off] = e;
            uint32_t la = smem_u32(&Bt[off]);
            #pragma unroll
            for (int rr = 1; rr < CSIZE; rr++)
                st_remote(la, (uint32_t)((rank + rr) & (CSIZE-1)), e);
        }
        cluster_sync_();
    }

    // ---- final cost: sum EA .* (G2*EB*G) + sum EA .* (G*EB*G2) ----
    float csum = 0.0f;

    acc[0]=acc[1]=acc[2]=0.0f;
    mm1x3(G2 + ig*PITCH, Bt + j0*PITCH, acc);             // U = G2 * EB
    U[trow*PITCH + j0+0] = acc[0];
    U[trow*PITCH + j0+1] = acc[1];
    U[trow*PITCH + j0+2] = acc[2];
    __syncthreads();
    acc[0]=acc[1]=acc[2]=0.0f;
    mm1x3(U + trow*PITCH, G + j0*PITCH, acc);             // T1 = U * G
    #pragma unroll
    for (int c = 0; c < 3; c++) csum += ea[c] * acc[c];
    __syncthreads();

    acc[0]=acc[1]=acc[2]=0.0f;
    mm1x3(G + ig*PITCH, Bt + j0*PITCH, acc);              // U = G * EB
    U[trow*PITCH + j0+0] = acc[0];
    U[trow*PITCH + j0+1] = acc[1];
    U[trow*PITCH + j0+2] = acc[2];
    __syncthreads();
    acc[0]=acc[1]=acc[2]=0.0f;
    mm1x3(U + trow*PITCH, G2 + j0*PITCH, acc);            // T2 = U * G2
    #pragma unroll
    for (int c = 0; c < 3; c++) csum += ea[c] * acc[c];

    csum = block_sum(csum, red);

    // cluster reduction: each rank deposits its partial into rank 0's red[16+rank]
    if (tid == 0) {
        if (rank == 0) {
            red[16] = csum;
        } else {
            st_remote(smem_u32(&red[16 + rank]), 0u, csum);
        }
    }
    cluster_sync_();
    if (rank == 0 && tid == 0)
        out[batch] = red[16] + red[17] + red[18] + red[19];
}

extern "C" void kernel_launch(void* const* d_in, const int* in_sizes, int n_in,
                              void* d_out, int out_size) {
    const float* img_pred   = (const float*)d_in[0];
    const float* img_target = (const float*)d_in[1];
    const float* cm         = (const float*)d_in[2];
    float* out = (float*)d_out;

    const int B = in_sizes[0] / (3 * NPIX);   // 32
    sinkhorn_kernel<<<B * CSIZE, NTHR>>>(img_pred, img_target, cm, out);
}